// round 3
// baseline (speedup 1.0000x reference)
#include <cuda_runtime.h>
#include <cstddef>

#define N_NODES 20000
#define N_EDGES 320000
#define N_GRAPHS 256
#define F_IN 128
#define HID 512
#define HCAT 2048   // 4*HID

// ---------------- scratch (static device globals; no allocations) ----------
__device__ float g_deg[N_NODES];
__device__ float g_dis[N_NODES];
__device__ int   g_cnt[N_NODES];
__device__ int   g_rowstart[N_NODES + 1];
__device__ int   g_cursor[N_NODES];
__device__ int   g_csr_src[N_EDGES];
__device__ float g_csr_w[N_EDGES];
__device__ int   g_gcount[N_GRAPHS];
__device__ int   g_gstart[N_GRAPHS + 1];
__device__ float g_tmp[(size_t)N_NODES * HID];   // 41 MB  (h = X @ W^T per layer)
__device__ float g_H[(size_t)N_NODES * HCAT];    // 164 MB (concat of h1..h4)

__device__ __forceinline__ float neg_inf() { return __int_as_float(0xff800000); }

// ---------------- graph preprocessing --------------------------------------
__global__ void k_init() {
    int i = blockIdx.x * blockDim.x + threadIdx.x;
    if (i < N_NODES) { g_deg[i] = 1.0f; g_cnt[i] = 0; g_cursor[i] = 0; }
    if (i < N_GRAPHS) g_gcount[i] = 0;
}

__global__ void k_edges_count(const int* __restrict__ ei) {
    int e = blockIdx.x * blockDim.x + threadIdx.x;
    if (e >= N_EDGES) return;
    int d = ei[N_EDGES + e];
    atomicAdd(&g_deg[d], 1.0f);
    atomicAdd(&g_cnt[d], 1);
}

__global__ void k_dis() {
    int i = blockIdx.x * blockDim.x + threadIdx.x;
    if (i < N_NODES) g_dis[i] = rsqrtf(g_deg[i]);   // deg >= 1 (self loop)
}

// exclusive prefix sum of g_cnt -> g_rowstart, single block of 512 threads
__global__ void k_scan_rows() {
    __shared__ int part[512];
    int t = threadIdx.x;
    const int CH = (N_NODES + 511) / 512;   // 40
    int base = t * CH;
    int s = 0;
    for (int j = 0; j < CH; j++) { int idx = base + j; if (idx < N_NODES) s += g_cnt[idx]; }
    part[t] = s;
    __syncthreads();
    for (int off = 1; off < 512; off <<= 1) {
        int v = (t >= off) ? part[t - off] : 0;
        __syncthreads();
        part[t] += v;
        __syncthreads();
    }
    int run = (t == 0) ? 0 : part[t - 1];
    for (int j = 0; j < CH; j++) {
        int idx = base + j;
        if (idx < N_NODES) { g_rowstart[idx] = run; run += g_cnt[idx]; }
    }
    if (t == 511) g_rowstart[N_NODES] = run;   // == N_EDGES
}

__global__ void k_edges_fill(const int* __restrict__ ei) {
    int e = blockIdx.x * blockDim.x + threadIdx.x;
    if (e >= N_EDGES) return;
    int s = ei[e];
    int d = ei[N_EDGES + e];
    int p = g_rowstart[d] + atomicAdd(&g_cursor[d], 1);
    g_csr_src[p] = s;
    g_csr_w[p] = g_dis[s] * g_dis[d];
}

__global__ void k_gcount(const int* __restrict__ batch) {
    int i = blockIdx.x * blockDim.x + threadIdx.x;
    if (i < N_NODES) atomicAdd(&g_gcount[batch[i]], 1);
}

__global__ void k_scan_g() {
    __shared__ int sh[N_GRAPHS];
    int t = threadIdx.x;
    sh[t] = g_gcount[t];
    __syncthreads();
    for (int off = 1; off < N_GRAPHS; off <<= 1) {
        int v = (t >= off) ? sh[t - off] : 0;
        __syncthreads();
        sh[t] += v;
        __syncthreads();
    }
    g_gstart[t + 1] = sh[t];
    if (t == 0) g_gstart[0] = 0;
}

// ---------------- GEMM: g_tmp = A @ W^T ------------------------------------
// A: [N_NODES, K] row-major with row stride lda; W: [HID, K] row-major.
// 128x128 tile, BK=8, 256 threads, 8x8 microtile.
__global__ void __launch_bounds__(256, 2) k_gemm(int layer, const float* __restrict__ X,
                                                 const float* __restrict__ W, int K) {
    const float* A; int lda;
    if (layer == 1) { A = X;                          lda = F_IN; }
    else            { A = &g_H[(size_t)(layer - 2) * HID]; lda = HCAT; }

    __shared__ float As[8][128];
    __shared__ float Ws[8][128];

    int t  = threadIdx.x;
    int m0 = blockIdx.y * 128, n0 = blockIdx.x * 128;
    int lr = t >> 1;            // tile row for loading (0..127)
    int lc = (t & 1) * 4;       // k offset for loading (0 or 4)
    int tm = (t >> 4) * 8;      // microtile row base
    int tn = (t & 15) * 8;      // microtile col base

    float acc[8][8];
#pragma unroll
    for (int i = 0; i < 8; i++)
#pragma unroll
        for (int j = 0; j < 8; j++) acc[i][j] = 0.0f;

    bool aok = (m0 + lr) < N_NODES;
    const float* Ap = A + (size_t)(m0 + lr) * lda + lc;
    const float* Wp = W + (size_t)(n0 + lr) * K + lc;

    for (int kk = 0; kk < K; kk += 8) {
        float4 av = aok ? *(const float4*)(Ap + kk) : make_float4(0.f, 0.f, 0.f, 0.f);
        float4 wv = *(const float4*)(Wp + kk);
        __syncthreads();
        As[lc + 0][lr] = av.x; As[lc + 1][lr] = av.y; As[lc + 2][lr] = av.z; As[lc + 3][lr] = av.w;
        Ws[lc + 0][lr] = wv.x; Ws[lc + 1][lr] = wv.y; Ws[lc + 2][lr] = wv.z; Ws[lc + 3][lr] = wv.w;
        __syncthreads();
#pragma unroll
        for (int k = 0; k < 8; k++) {
            float4 a0 = *(const float4*)&As[k][tm];
            float4 a1 = *(const float4*)&As[k][tm + 4];
            float4 w0 = *(const float4*)&Ws[k][tn];
            float4 w1 = *(const float4*)&Ws[k][tn + 4];
            float a[8] = {a0.x, a0.y, a0.z, a0.w, a1.x, a1.y, a1.z, a1.w};
            float w[8] = {w0.x, w0.y, w0.z, w0.w, w1.x, w1.y, w1.z, w1.w};
#pragma unroll
            for (int i = 0; i < 8; i++)
#pragma unroll
                for (int j = 0; j < 8; j++) acc[i][j] += a[i] * w[j];
        }
    }

#pragma unroll
    for (int i = 0; i < 8; i++) {
        int row = m0 + tm + i;
        if (row < N_NODES) {
            float4 o0 = make_float4(acc[i][0], acc[i][1], acc[i][2], acc[i][3]);
            float4 o1 = make_float4(acc[i][4], acc[i][5], acc[i][6], acc[i][7]);
            *(float4*)&g_tmp[(size_t)row * HID + n0 + tn]     = o0;
            *(float4*)&g_tmp[(size_t)row * HID + n0 + tn + 4] = o1;
        }
    }
}

// ---------------- SpMM: H[:, coloff:coloff+512] = Ahat @ g_tmp + bias ------
// one block per node, 128 threads x float4 columns, CSR gather, no atomics
__global__ void __launch_bounds__(128) k_spmm(const float* __restrict__ bias, int coloff) {
    int i = blockIdx.x;
    int c = threadIdx.x * 4;
    float dii = g_dis[i];
    float sw = dii * dii;                               // self-loop norm
    float4 tv = *(const float4*)&g_tmp[(size_t)i * HID + c];
    float4 bv = *(const float4*)&bias[c];
    float ax = sw * tv.x + bv.x;
    float ay = sw * tv.y + bv.y;
    float az = sw * tv.z + bv.z;
    float aw = sw * tv.w + bv.w;
    int e  = g_rowstart[i];
    int e1 = g_rowstart[i + 1];
    for (; e < e1; e++) {
        int s = g_csr_src[e];
        float w = g_csr_w[e];
        float4 v = *(const float4*)&g_tmp[(size_t)s * HID + c];
        ax += w * v.x; ay += w * v.y; az += w * v.z; aw += w * v.w;
    }
    float4 o = make_float4(ax, ay, az, aw);
    *(float4*)&g_H[(size_t)i * HCAT + coloff + c] = o;
}

// ---------------- pooling: out = [segmax(H), segmean(H>0)] -----------------
__global__ void k_pool(float* __restrict__ out) {
    int col = blockIdx.x * blockDim.x + threadIdx.x;    // 0..2047
    int g   = blockIdx.y;
    int i0 = g_gstart[g], i1 = g_gstart[g + 1];
    float mx = neg_inf();
    float pos = 0.0f;
    for (int i = i0; i < i1; i++) {
        float v = g_H[(size_t)i * HCAT + col];
        mx = fmaxf(mx, v);
        pos += (v > 0.0f) ? 1.0f : 0.0f;
    }
    int cnt = i1 - i0;
    out[(size_t)g * (2 * HCAT) + col] = mx;             // -inf if empty (jax identity)
    out[(size_t)g * (2 * HCAT) + HCAT + col] = (cnt > 0) ? pos / (float)cnt : 0.0f;
}

// ---------------- launch ----------------------------------------------------
extern "C" void kernel_launch(void* const* d_in, const int* in_sizes, int n_in,
                              void* d_out, int out_size) {
    const float* x     = (const float*)d_in[0];
    const int*   ei    = (const int*)d_in[1];
    const int*   batch = (const int*)d_in[2];
    // d_in[3]=lin_W, d_in[4]=lin_b : dead code in reference
    const float* W1 = (const float*)d_in[5];  const float* b1 = (const float*)d_in[6];
    const float* W2 = (const float*)d_in[7];  const float* b2 = (const float*)d_in[8];
    const float* W3 = (const float*)d_in[9];  const float* b3 = (const float*)d_in[10];
    const float* W4 = (const float*)d_in[11]; const float* b4 = (const float*)d_in[12];
    float* out = (float*)d_out;

    const int TB = 256;
    k_init<<<(N_NODES + TB - 1) / TB, TB>>>();
    k_edges_count<<<(N_EDGES + TB - 1) / TB, TB>>>(ei);
    k_dis<<<(N_NODES + TB - 1) / TB, TB>>>();
    k_scan_rows<<<1, 512>>>();
    k_edges_fill<<<(N_EDGES + TB - 1) / TB, TB>>>(ei);
    k_gcount<<<(N_NODES + TB - 1) / TB, TB>>>(batch);
    k_scan_g<<<1, N_GRAPHS>>>();

    dim3 ggrid(HID / 128, (N_NODES + 127) / 128);   // (4, 157)

    k_gemm<<<ggrid, 256>>>(1, x, W1, F_IN);
    k_spmm<<<N_NODES, 128>>>(b1, 0);

    k_gemm<<<ggrid, 256>>>(2, x, W2, HID);
    k_spmm<<<N_NODES, 128>>>(b2, HID);

    k_gemm<<<ggrid, 256>>>(3, x, W3, HID);
    k_spmm<<<N_NODES, 128>>>(b3, 2 * HID);

    k_gemm<<<ggrid, 256>>>(4, x, W4, HID);
    k_spmm<<<N_NODES, 128>>>(b4, 3 * HID);

    dim3 pgrid(HCAT / 256, N_GRAPHS);
    k_pool<<<pgrid, 256>>>(out);
}

// round 7
// speedup vs baseline: 2.1428x; 2.1428x over previous
#include <cuda_runtime.h>
#include <cuda_bf16.h>
#include <cstddef>
#include <cstdint>

#define N_NODES 20000
#define N_EDGES 320000
#define N_GRAPHS 256
#define F_IN 128
#define HID 512
#define HCAT 2048   // 4*HID

// ---------------- scratch (static device globals; no allocations) ----------
__device__ float g_deg[N_NODES];
__device__ float g_dis[N_NODES];
__device__ int   g_cnt[N_NODES];
__device__ int   g_rowstart[N_NODES + 1];
__device__ int   g_cursor[N_NODES];
__device__ int   g_csr_src[N_EDGES];
__device__ float g_csr_w[N_EDGES];
__device__ int   g_gcount[N_GRAPHS];
__device__ int   g_gstart[N_GRAPHS + 1];
__device__ float g_tmp[(size_t)N_NODES * HID];   // 41 MB  (h = A @ W^T per layer)
__device__ float g_H[(size_t)N_NODES * HCAT];    // 164 MB (concat of h1..h4)
// bf16 split operands
__device__ __nv_bfloat16 g_Ahi[(size_t)N_NODES * HID];
__device__ __nv_bfloat16 g_Alo[(size_t)N_NODES * HID];
__device__ __nv_bfloat16 g_Whi[HID * HID];
__device__ __nv_bfloat16 g_Wlo[HID * HID];

__device__ __forceinline__ float neg_inf() { return __int_as_float(0xff800000); }

// ---------------- low-level helpers ----------------------------------------
__device__ __forceinline__ uint32_t smem_u32(const void* p) {
    uint32_t a;
    asm("{ .reg .u64 t; cvta.to.shared.u64 t, %1; cvt.u32.u64 %0, t; }" : "=r"(a) : "l"(p));
    return a;
}
__device__ __forceinline__ void cpa16(uint32_t dst, const void* src, int sz) {
    asm volatile("cp.async.cg.shared.global [%0], [%1], 16, %2;"
                 :: "r"(dst), "l"(src), "r"(sz) : "memory");
}
__device__ __forceinline__ void ldsm4(uint32_t* r, uint32_t addr) {
    asm volatile("ldmatrix.sync.aligned.m8n8.x4.shared.b16 {%0,%1,%2,%3}, [%4];"
                 : "=r"(r[0]), "=r"(r[1]), "=r"(r[2]), "=r"(r[3]) : "r"(addr));
}
__device__ __forceinline__ void mma16816(float* c, const uint32_t* a, const uint32_t* b) {
    asm volatile("mma.sync.aligned.m16n8k16.row.col.f32.bf16.bf16.f32 "
                 "{%0,%1,%2,%3}, {%4,%5,%6,%7}, {%8,%9}, {%0,%1,%2,%3};"
                 : "+f"(c[0]), "+f"(c[1]), "+f"(c[2]), "+f"(c[3])
                 : "r"(a[0]), "r"(a[1]), "r"(a[2]), "r"(a[3]), "r"(b[0]), "r"(b[1]));
}
__device__ __forceinline__ uint32_t pack2(__nv_bfloat16 a, __nv_bfloat16 b) {
    return (uint32_t)__bfloat16_as_ushort(a) | ((uint32_t)__bfloat16_as_ushort(b) << 16);
}
// physical smem offset of 16B chunk (row, c16) in a 128x32 bf16 tile,
// 2 rows per 128B line, 8 chunks per line XOR-swizzled by line -> ldmatrix
// (8 rows x fixed c16) is bank-conflict-free.
__device__ __forceinline__ uint32_t phys(int row, int c16) {
    uint32_t line = (uint32_t)(row >> 1);
    uint32_t c8 = (uint32_t)(((row & 1) << 2) | c16) ^ (line & 7u);
    return line * 128u + c8 * 16u;
}

// ---------------- graph preprocessing --------------------------------------
__global__ void k_init() {
    int i = blockIdx.x * blockDim.x + threadIdx.x;
    if (i < N_NODES) { g_deg[i] = 1.0f; g_cnt[i] = 0; g_cursor[i] = 0; }
    if (i < N_GRAPHS) g_gcount[i] = 0;
}

__global__ void k_edges_count(const int* __restrict__ ei) {
    int e = blockIdx.x * blockDim.x + threadIdx.x;
    if (e >= N_EDGES) return;
    int d = ei[N_EDGES + e];
    atomicAdd(&g_deg[d], 1.0f);
    atomicAdd(&g_cnt[d], 1);
}

__global__ void k_dis() {
    int i = blockIdx.x * blockDim.x + threadIdx.x;
    if (i < N_NODES) g_dis[i] = rsqrtf(g_deg[i]);
}

__global__ void k_scan_rows() {
    __shared__ int part[512];
    int t = threadIdx.x;
    const int CH = (N_NODES + 511) / 512;
    int base = t * CH;
    int s = 0;
    for (int j = 0; j < CH; j++) { int idx = base + j; if (idx < N_NODES) s += g_cnt[idx]; }
    part[t] = s;
    __syncthreads();
    for (int off = 1; off < 512; off <<= 1) {
        int v = (t >= off) ? part[t - off] : 0;
        __syncthreads();
        part[t] += v;
        __syncthreads();
    }
    int run = (t == 0) ? 0 : part[t - 1];
    for (int j = 0; j < CH; j++) {
        int idx = base + j;
        if (idx < N_NODES) { g_rowstart[idx] = run; run += g_cnt[idx]; }
    }
    if (t == 511) g_rowstart[N_NODES] = run;
}

__global__ void k_edges_fill(const int* __restrict__ ei) {
    int e = blockIdx.x * blockDim.x + threadIdx.x;
    if (e >= N_EDGES) return;
    int s = ei[e];
    int d = ei[N_EDGES + e];
    int p = g_rowstart[d] + atomicAdd(&g_cursor[d], 1);
    g_csr_src[p] = s;
    g_csr_w[p] = g_dis[s] * g_dis[d];
}

__global__ void k_gcount(const int* __restrict__ batch) {
    int i = blockIdx.x * blockDim.x + threadIdx.x;
    if (i < N_NODES) atomicAdd(&g_gcount[batch[i]], 1);
}

__global__ void k_scan_g() {
    __shared__ int sh[N_GRAPHS];
    int t = threadIdx.x;
    sh[t] = g_gcount[t];
    __syncthreads();
    for (int off = 1; off < N_GRAPHS; off <<= 1) {
        int v = (t >= off) ? sh[t - off] : 0;
        __syncthreads();
        sh[t] += v;
        __syncthreads();
    }
    g_gstart[t + 1] = sh[t];
    if (t == 0) g_gstart[0] = 0;
}

// ---------------- fp32 -> bf16 hi/lo split ----------------------------------
__global__ void k_convert(const float* __restrict__ A, int lda, int K, int rows,
                          __nv_bfloat16* __restrict__ Hi, __nv_bfloat16* __restrict__ Lo) {
    int id = blockIdx.x * blockDim.x + threadIdx.x;     // one float4
    int tot = rows * (K / 4);
    if (id >= tot) return;
    int row = id / (K / 4), c4 = id % (K / 4);
    float4 v = *(const float4*)(A + (size_t)row * lda + c4 * 4);
    __nv_bfloat16 h0 = __float2bfloat16_rn(v.x);
    __nv_bfloat16 h1 = __float2bfloat16_rn(v.y);
    __nv_bfloat16 h2 = __float2bfloat16_rn(v.z);
    __nv_bfloat16 h3 = __float2bfloat16_rn(v.w);
    __nv_bfloat16 l0 = __float2bfloat16_rn(v.x - __bfloat162float(h0));
    __nv_bfloat16 l1 = __float2bfloat16_rn(v.y - __bfloat162float(h1));
    __nv_bfloat16 l2 = __float2bfloat16_rn(v.z - __bfloat162float(h2));
    __nv_bfloat16 l3 = __float2bfloat16_rn(v.w - __bfloat162float(h3));
    *(uint2*)(Hi + (size_t)row * K + c4 * 4) = make_uint2(pack2(h0, h1), pack2(h2, h3));
    *(uint2*)(Lo + (size_t)row * K + c4 * 4) = make_uint2(pack2(l0, l1), pack2(l2, l3));
}

// ---------------- bf16 split-3 tensor-core GEMM: g_tmp = A @ W^T ------------
// CTA 128x128, 256 threads (8 warps, 2x4 -> warp tile 64x32), K-chunk 32.
// smem per buffer: Ahi|Alo|Bhi|Blo, each 128x32 bf16 = 8KB -> 32KB; x2 buffers.
#define SMB (2 * 32768 + 1024)

__global__ void __launch_bounds__(256) k_mma_bf16(
    const __nv_bfloat16* __restrict__ Ahi, const __nv_bfloat16* __restrict__ Alo,
    const __nv_bfloat16* __restrict__ Bhi, const __nv_bfloat16* __restrict__ Blo,
    int K) {
    extern __shared__ char smraw[];
    uint32_t sb = smem_u32(smraw);
    uint32_t base = (sb + 1023u) & ~1023u;

    int t = threadIdx.x, lane = t & 31, w = t >> 5;
    int wm = (w & 1) * 64, wn = (w >> 1) * 32;
    int m0 = blockIdx.y * 128, n0 = blockIdx.x * 128;

    float c[4][4][4];
#pragma unroll
    for (int i = 0; i < 4; i++)
#pragma unroll
        for (int j = 0; j < 4; j++)
#pragma unroll
            for (int r = 0; r < 4; r++) c[i][j][r] = 0.0f;

    const int kt = K / 32;

    // ldmatrix lane geometry (same for A x4 and B x4)
    int lrow = (lane & 7) | (((lane >> 3) & 1) << 3);
    int lc = lane >> 4;

    // --- cp.async issue of one K-chunk into buffer b ---
    auto issue = [&](int ci, int b) {
        int k0 = ci * 32;
        uint32_t bufb = base + (uint32_t)b * 32768u;
#pragma unroll
        for (int j = 0; j < 2; j++) {
            int id = t + j * 256;
            int row = id >> 2, c16 = id & 3;
            uint32_t off = phys(row, c16);
            int ra = m0 + row;
            int sz = (ra < N_NODES) ? 16 : 0;
            if (ra >= N_NODES) ra = N_NODES - 1;
            const __nv_bfloat16* sa = Ahi + (size_t)ra * K + k0 + c16 * 8;
            const __nv_bfloat16* sal = Alo + (size_t)ra * K + k0 + c16 * 8;
            cpa16(bufb + off, sa, sz);
            cpa16(bufb + 8192u + off, sal, sz);
            const __nv_bfloat16* sbp = Bhi + (size_t)(n0 + row) * K + k0 + c16 * 8;
            const __nv_bfloat16* sbl = Blo + (size_t)(n0 + row) * K + k0 + c16 * 8;
            cpa16(bufb + 16384u + off, sbp, 16);
            cpa16(bufb + 24576u + off, sbl, 16);
        }
    };

    issue(0, 0);
    asm volatile("cp.async.commit_group;" ::: "memory");

    for (int ci = 0; ci < kt; ci++) {
        if (ci + 1 < kt) {
            issue(ci + 1, (ci + 1) & 1);
            asm volatile("cp.async.commit_group;" ::: "memory");
            asm volatile("cp.async.wait_group 1;" ::: "memory");
        } else {
            asm volatile("cp.async.wait_group 0;" ::: "memory");
        }
        __syncthreads();

        uint32_t buf = base + (uint32_t)(ci & 1) * 32768u;
#pragma unroll
        for (int s = 0; s < 2; s++) {
            uint32_t ah[4][4], al[4][4], bh[4][2], bl[4][2];
#pragma unroll
            for (int mt = 0; mt < 4; mt++) {
                uint32_t off = phys(wm + mt * 16 + lrow, s * 2 + lc);
                ldsm4(ah[mt], buf + off);
                ldsm4(al[mt], buf + 8192u + off);
            }
#pragma unroll
            for (int p = 0; p < 2; p++) {
                uint32_t off = phys(wn + p * 16 + lrow, s * 2 + lc);
                uint32_t r[4];
                ldsm4(r, buf + 16384u + off);
                bh[2 * p][0] = r[0]; bh[2 * p + 1][0] = r[1];
                bh[2 * p][1] = r[2]; bh[2 * p + 1][1] = r[3];
                ldsm4(r, buf + 24576u + off);
                bl[2 * p][0] = r[0]; bl[2 * p + 1][0] = r[1];
                bl[2 * p][1] = r[2]; bl[2 * p + 1][1] = r[3];
            }
#pragma unroll
            for (int mt = 0; mt < 4; mt++)
#pragma unroll
                for (int nt = 0; nt < 4; nt++) {
                    mma16816(c[mt][nt], ah[mt], bh[nt]);
                    mma16816(c[mt][nt], ah[mt], bl[nt]);
                    mma16816(c[mt][nt], al[mt], bh[nt]);
                }
        }
        __syncthreads();
    }

    // epilogue: D frag (row = lane/4 (+8), col = (lane%4)*2 (+1))
    int er = lane >> 2, ec = (lane & 3) * 2;
#pragma unroll
    for (int mt = 0; mt < 4; mt++) {
#pragma unroll
        for (int nt = 0; nt < 4; nt++) {
            int row0 = m0 + wm + mt * 16 + er;
            int col = n0 + wn + nt * 8 + ec;
            if (row0 < N_NODES)
                *(float2*)&g_tmp[(size_t)row0 * HID + col] = make_float2(c[mt][nt][0], c[mt][nt][1]);
            if (row0 + 8 < N_NODES)
                *(float2*)&g_tmp[(size_t)(row0 + 8) * HID + col] = make_float2(c[mt][nt][2], c[mt][nt][3]);
        }
    }
}

// ---------------- SpMM: H[:, coloff:coloff+512] = Ahat @ g_tmp + bias ------
__global__ void __launch_bounds__(128) k_spmm(const float* __restrict__ bias, int coloff) {
    int i = blockIdx.x;
    int c = threadIdx.x * 4;
    float dii = g_dis[i];
    float sw = dii * dii;
    float4 tv = *(const float4*)&g_tmp[(size_t)i * HID + c];
    float4 bv = *(const float4*)&bias[c];
    float ax = sw * tv.x + bv.x;
    float ay = sw * tv.y + bv.y;
    float az = sw * tv.z + bv.z;
    float aw = sw * tv.w + bv.w;
    int e  = g_rowstart[i];
    int e1 = g_rowstart[i + 1];
    for (; e < e1; e++) {
        int s = g_csr_src[e];
        float w = g_csr_w[e];
        float4 v = *(const float4*)&g_tmp[(size_t)s * HID + c];
        ax += w * v.x; ay += w * v.y; az += w * v.z; aw += w * v.w;
    }
    *(float4*)&g_H[(size_t)i * HCAT + coloff + c] = make_float4(ax, ay, az, aw);
}

// ---------------- pooling: out = [segmax(H), segmean(H>0)] -----------------
__global__ void k_pool(float* __restrict__ out) {
    int col = blockIdx.x * blockDim.x + threadIdx.x;
    int g   = blockIdx.y;
    int i0 = g_gstart[g], i1 = g_gstart[g + 1];
    float mx = neg_inf();
    float pos = 0.0f;
    for (int i = i0; i < i1; i++) {
        float v = g_H[(size_t)i * HCAT + col];
        mx = fmaxf(mx, v);
        pos += (v > 0.0f) ? 1.0f : 0.0f;
    }
    int cnt = i1 - i0;
    out[(size_t)g * (2 * HCAT) + col] = mx;
    out[(size_t)g * (2 * HCAT) + HCAT + col] = (cnt > 0) ? pos / (float)cnt : 0.0f;
}

// ---------------- launch ----------------------------------------------------
extern "C" void kernel_launch(void* const* d_in, const int* in_sizes, int n_in,
                              void* d_out, int out_size) {
    const float* x     = (const float*)d_in[0];
    const int*   ei    = (const int*)d_in[1];
    const int*   batch = (const int*)d_in[2];
    // d_in[3]=lin_W, d_in[4]=lin_b : dead code in reference
    const float* W1 = (const float*)d_in[5];  const float* b1 = (const float*)d_in[6];
    const float* W2 = (const float*)d_in[7];  const float* b2 = (const float*)d_in[8];
    const float* W3 = (const float*)d_in[9];  const float* b3 = (const float*)d_in[10];
    const float* W4 = (const float*)d_in[11]; const float* b4 = (const float*)d_in[12];
    float* out = (float*)d_out;

    // device addresses of __device__ symbols (host code must NOT use symbols directly)
    float *p_H;
    __nv_bfloat16 *p_Ahi, *p_Alo, *p_Whi, *p_Wlo;
    cudaGetSymbolAddress((void**)&p_H,   g_H);
    cudaGetSymbolAddress((void**)&p_Ahi, g_Ahi);
    cudaGetSymbolAddress((void**)&p_Alo, g_Alo);
    cudaGetSymbolAddress((void**)&p_Whi, g_Whi);
    cudaGetSymbolAddress((void**)&p_Wlo, g_Wlo);

    cudaFuncSetAttribute(k_mma_bf16, cudaFuncAttributeMaxDynamicSharedMemorySize, SMB);

    const int TB = 256;
    k_init<<<(N_NODES + TB - 1) / TB, TB>>>();
    k_edges_count<<<(N_EDGES + TB - 1) / TB, TB>>>(ei);
    k_dis<<<(N_NODES + TB - 1) / TB, TB>>>();
    k_scan_rows<<<1, 512>>>();
    k_edges_fill<<<(N_EDGES + TB - 1) / TB, TB>>>(ei);
    k_gcount<<<(N_NODES + TB - 1) / TB, TB>>>(batch);
    k_scan_g<<<1, N_GRAPHS>>>();

    dim3 mg(HID / 128, (N_NODES + 127) / 128);   // (4, 157)

    auto run_layer = [&](const float* A, int lda, const float* W, const float* b,
                         int K, int coloff) {
        int totA = N_NODES * (K / 4);
        int totW = HID * (K / 4);
        k_convert<<<(totA + 255) / 256, 256>>>(A, lda, K, N_NODES, p_Ahi, p_Alo);
        k_convert<<<(totW + 255) / 256, 256>>>(W, K, K, HID, p_Whi, p_Wlo);
        k_mma_bf16<<<mg, 256, SMB>>>(p_Ahi, p_Alo, p_Whi, p_Wlo, K);
        k_spmm<<<N_NODES, 128>>>(b, coloff);
    };

    run_layer(x, F_IN, W1, b1, F_IN, 0);
    run_layer(p_H + 0 * HID, HCAT, W2, b2, HID, HID);
    run_layer(p_H + 1 * HID, HCAT, W3, b3, HID, 2 * HID);
    run_layer(p_H + 2 * HID, HCAT, W4, b4, HID, 3 * HID);

    dim3 pgrid(HCAT / 256, N_GRAPHS);
    k_pool<<<pgrid, 256>>>(out);
}

// round 11
// speedup vs baseline: 3.3409x; 1.5591x over previous
#include <cuda_runtime.h>
#include <cuda_bf16.h>
#include <cstddef>
#include <cstdint>

#define N_NODES 20000
#define N_EDGES 320000
#define N_GRAPHS 256
#define F_IN 128
#define HID 512
#define HCAT 2048   // 4*HID
#define USZ (HID * F_IN)   // 512*128

// ---------------- scratch (static device globals; no allocations) ----------
__device__ float g_deg[N_NODES];
__device__ float g_dis[N_NODES];
__device__ int   g_cnt[N_NODES];
__device__ int   g_rowstart[N_NODES + 1];
__device__ int   g_cursor[N_NODES];
__device__ int   g_csr_src[N_EDGES];
__device__ float g_csr_w[N_EDGES];
__device__ int   g_gcount[N_GRAPHS];
__device__ int   g_gstart[N_GRAPHS + 1];

__device__ float g_Pa[(size_t)N_NODES * F_IN];    // P ping
__device__ float g_Pb[(size_t)N_NODES * F_IN];    // P pong
__device__ __nv_bfloat16 g_Phi[(size_t)N_NODES * F_IN];
__device__ __nv_bfloat16 g_Plo[(size_t)N_NODES * F_IN];
__device__ float g_q[3][N_NODES];                 // q1,q2,q3
__device__ float g_U[2][USZ];                     // weight-product ping-pong (fp32)
__device__ __nv_bfloat16 g_Uhi[4 * USZ];          // U1..U4 bf16 hi
__device__ __nv_bfloat16 g_Ulo[4 * USZ];          // U1..U4 bf16 lo
__device__ float g_c[6][HID];                     // c21,c32,c43,c31,c42,c41
__device__ float g_H[(size_t)N_NODES * HCAT];     // concat h1..h4 (pool input)

__device__ __forceinline__ float neg_inf() { return __int_as_float(0xff800000); }

// ---------------- low-level helpers ----------------------------------------
__device__ __forceinline__ uint32_t smem_u32(const void* p) {
    uint32_t a;
    asm("{ .reg .u64 t; cvta.to.shared.u64 t, %1; cvt.u32.u64 %0, t; }" : "=r"(a) : "l"(p));
    return a;
}
__device__ __forceinline__ void cpa16(uint32_t dst, const void* src, int sz) {
    asm volatile("cp.async.cg.shared.global [%0], [%1], 16, %2;"
                 :: "r"(dst), "l"(src), "r"(sz) : "memory");
}
__device__ __forceinline__ void ldsm4(uint32_t* r, uint32_t addr) {
    asm volatile("ldmatrix.sync.aligned.m8n8.x4.shared.b16 {%0,%1,%2,%3}, [%4];"
                 : "=r"(r[0]), "=r"(r[1]), "=r"(r[2]), "=r"(r[3]) : "r"(addr));
}
__device__ __forceinline__ void mma16816(float* c, const uint32_t* a, const uint32_t* b) {
    asm volatile("mma.sync.aligned.m16n8k16.row.col.f32.bf16.bf16.f32 "
                 "{%0,%1,%2,%3}, {%4,%5,%6,%7}, {%8,%9}, {%0,%1,%2,%3};"
                 : "+f"(c[0]), "+f"(c[1]), "+f"(c[2]), "+f"(c[3])
                 : "r"(a[0]), "r"(a[1]), "r"(a[2]), "r"(a[3]), "r"(b[0]), "r"(b[1]));
}
__device__ __forceinline__ uint32_t pack2(__nv_bfloat16 a, __nv_bfloat16 b) {
    return (uint32_t)__bfloat16_as_ushort(a) | ((uint32_t)__bfloat16_as_ushort(b) << 16);
}
__device__ __forceinline__ uint32_t phys(int row, int c16) {
    uint32_t line = (uint32_t)(row >> 1);
    uint32_t c8 = (uint32_t)(((row & 1) << 2) | c16) ^ (line & 7u);
    return line * 128u + c8 * 16u;
}
__device__ __forceinline__ void split1(float v, __nv_bfloat16& h, __nv_bfloat16& l) {
    h = __float2bfloat16_rn(v);
    l = __float2bfloat16_rn(v - __bfloat162float(h));
}

// ---------------- graph preprocessing --------------------------------------
__global__ void k_init() {
    int i = blockIdx.x * blockDim.x + threadIdx.x;
    if (i < N_NODES) { g_deg[i] = 1.0f; g_cnt[i] = 0; g_cursor[i] = 0; }
    if (i < N_GRAPHS) g_gcount[i] = 0;
}

__global__ void k_count(const int* __restrict__ ei, const int* __restrict__ batch) {
    int i = blockIdx.x * blockDim.x + threadIdx.x;
    if (i < N_EDGES) {
        int d = ei[N_EDGES + i];
        atomicAdd(&g_deg[d], 1.0f);
        atomicAdd(&g_cnt[d], 1);
    }
    if (i < N_NODES) atomicAdd(&g_gcount[batch[i]], 1);
}

// prefix sum of cnt -> rowstart, plus dis = rsqrt(deg)
__global__ void k_scan_rows() {
    __shared__ int part[512];
    int t = threadIdx.x;
    const int CH = (N_NODES + 511) / 512;
    int base = t * CH;
    int s = 0;
    for (int j = 0; j < CH; j++) {
        int idx = base + j;
        if (idx < N_NODES) { s += g_cnt[idx]; g_dis[idx] = rsqrtf(g_deg[idx]); }
    }
    part[t] = s;
    __syncthreads();
    for (int off = 1; off < 512; off <<= 1) {
        int v = (t >= off) ? part[t - off] : 0;
        __syncthreads();
        part[t] += v;
        __syncthreads();
    }
    int run = (t == 0) ? 0 : part[t - 1];
    for (int j = 0; j < CH; j++) {
        int idx = base + j;
        if (idx < N_NODES) { g_rowstart[idx] = run; run += g_cnt[idx]; }
    }
    if (t == 511) g_rowstart[N_NODES] = run;
}

__global__ void k_edges_fill(const int* __restrict__ ei) {
    int e = blockIdx.x * blockDim.x + threadIdx.x;
    if (e >= N_EDGES) return;
    int s = ei[e];
    int d = ei[N_EDGES + e];
    int p = g_rowstart[d] + atomicAdd(&g_cursor[d], 1);
    g_csr_src[p] = s;
    g_csr_w[p] = g_dis[s] * g_dis[d];
}

__global__ void k_scan_g() {
    __shared__ int sh[N_GRAPHS];
    int t = threadIdx.x;
    sh[t] = g_gcount[t];
    __syncthreads();
    for (int off = 1; off < N_GRAPHS; off <<= 1) {
        int v = (t >= off) ? sh[t - off] : 0;
        __syncthreads();
        sh[t] += v;
        __syncthreads();
    }
    g_gstart[t + 1] = sh[t];
    if (t == 0) g_gstart[0] = 0;
}

// ---------------- weight chain ----------------------------------------------
// convert W1 -> g_Uhi[0], g_Ulo[0]
__global__ void k_convW1(const float* __restrict__ W1) {
    int id = blockIdx.x * blockDim.x + threadIdx.x;   // one float4
    if (id >= HID * (F_IN / 4)) return;
    float4 v = *(const float4*)(W1 + (size_t)id * 4);
    __nv_bfloat16 h0, h1, h2, h3, l0, l1, l2, l3;
    split1(v.x, h0, l0); split1(v.y, h1, l1); split1(v.z, h2, l2); split1(v.w, h3, l3);
    ((uint2*)g_Uhi)[id] = make_uint2(pack2(h0, h1), pack2(h2, h3));
    ((uint2*)g_Ulo)[id] = make_uint2(pack2(l0, l1), pack2(l2, l3));
}

// Uout = Wb[512,512] @ Uin[512,128]; fp32; also bf16-split into slot split_idx
__global__ void k_wprod(const float* __restrict__ Wb, const float* __restrict__ Uext,
                        int use_ext, int in_idx, int out_idx, int split_idx) {
    __shared__ float As[32][33], Bs[32][33];
    const float* Uin = use_ext ? Uext : g_U[in_idx];
    float* Uout = g_U[out_idx];
    int t = threadIdx.x;
    int tx = t & 15, ty = t >> 4;
    int m0 = blockIdx.y * 32, n0 = blockIdx.x * 32;
    float acc[2][2] = {{0.f, 0.f}, {0.f, 0.f}};
    for (int k0 = 0; k0 < HID; k0 += 32) {
#pragma unroll
        for (int j = 0; j < 4; j++) {
            int idx = t + j * 256;
            int r = idx >> 5, cc = idx & 31;
            As[r][cc] = Wb[(size_t)(m0 + r) * HID + k0 + cc];
            Bs[r][cc] = Uin[(size_t)(k0 + r) * F_IN + n0 + cc];
        }
        __syncthreads();
#pragma unroll
        for (int kk = 0; kk < 32; kk++) {
            float a0 = As[ty * 2][kk], a1 = As[ty * 2 + 1][kk];
            float b0 = Bs[kk][tx * 2], b1 = Bs[kk][tx * 2 + 1];
            acc[0][0] += a0 * b0; acc[0][1] += a0 * b1;
            acc[1][0] += a1 * b0; acc[1][1] += a1 * b1;
        }
        __syncthreads();
    }
#pragma unroll
    for (int i = 0; i < 2; i++)
#pragma unroll
        for (int j = 0; j < 2; j++) {
            int m = m0 + ty * 2 + i, n = n0 + tx * 2 + j;
            float v = acc[i][j];
            Uout[(size_t)m * F_IN + n] = v;
            __nv_bfloat16 h, l;
            split1(v, h, l);
            g_Uhi[(size_t)split_idx * USZ + (size_t)m * F_IN + n] = h;
            g_Ulo[(size_t)split_idx * USZ + (size_t)m * F_IN + n] = l;
        }
}

// out[i] = sum_j W[i,j] * v[j] ; v from ext pointer or g_c[vin]
__global__ void k_matvec(const float* __restrict__ W, const float* __restrict__ vext,
                         int use_ext, int vin, int out_idx) {
    __shared__ float red[128];
    int i = blockIdx.x;
    const float* v = use_ext ? vext : g_c[vin];
    float p = 0.f;
    for (int j = threadIdx.x; j < HID; j += 128) p += W[(size_t)i * HID + j] * v[j];
    red[threadIdx.x] = p;
    __syncthreads();
    for (int off = 64; off > 0; off >>= 1) {
        if (threadIdx.x < off) red[threadIdx.x] += red[threadIdx.x + off];
        __syncthreads();
    }
    if (threadIdx.x == 0) g_c[out_idx][i] = red[0];
}

// ---------------- SpMM on 128 cols: P_k = Ahat @ P_{k-1}; q_k = Ahat q_{k-1}
// warp per node; lane = one float4 (4 cols). Writes fp32 P + bf16 hi/lo split.
__global__ void __launch_bounds__(256) k_spmm_p(const float* __restrict__ xin, int layer) {
    int gw = (blockIdx.x * 256 + threadIdx.x) >> 5;
    if (gw >= N_NODES) return;
    int lane = threadIdx.x & 31;

    const float* Pin = (layer == 0) ? xin : ((layer & 1) ? g_Pa : g_Pb);
    float* Pout = (layer & 1) ? g_Pb : g_Pa;
    const float* qin = (layer == 0) ? nullptr : g_q[layer - 1];

    float dii = g_dis[gw];
    float sw = dii * dii;
    const float4* __restrict__ Pi4 = (const float4*)Pin;
    float4 v = Pi4[(size_t)gw * 32 + lane];
    float4 acc = make_float4(sw * v.x, sw * v.y, sw * v.z, sw * v.w);
    float qacc = sw * (qin ? qin[gw] : 1.0f);

    int e = g_rowstart[gw], e1 = g_rowstart[gw + 1];
    for (; e < e1; e++) {
        int s = g_csr_src[e];
        float w = g_csr_w[e];
        float4 u = Pi4[(size_t)s * 32 + lane];
        acc.x += w * u.x; acc.y += w * u.y; acc.z += w * u.z; acc.w += w * u.w;
        if (lane == 0) qacc += w * (qin ? qin[s] : 1.0f);
    }

    if (layer < 3) ((float4*)Pout)[(size_t)gw * 32 + lane] = acc;
    __nv_bfloat16 h0, h1, h2, h3, l0, l1, l2, l3;
    split1(acc.x, h0, l0); split1(acc.y, h1, l1);
    split1(acc.z, h2, l2); split1(acc.w, h3, l3);
    ((uint2*)g_Phi)[(size_t)gw * 32 + lane] = make_uint2(pack2(h0, h1), pack2(h2, h3));
    ((uint2*)g_Plo)[(size_t)gw * 32 + lane] = make_uint2(pack2(l0, l1), pack2(l2, l3));
    if (layer < 3 && lane == 0) g_q[layer][gw] = qacc;
}

// ---------------- bf16 split-3 tensor-core GEMM: h_k = P_k U_k^T + rank1 ----
// CTA 128x128, 256 threads (8 warps, warp tile 64x32), K=128 (4 chunks of 32).
#define SMB (2 * 32768 + 1024)

__global__ void __launch_bounds__(256) k_mma_p(int layer, const float* __restrict__ bias) {
    extern __shared__ char smraw[];
    uint32_t sb = smem_u32(smraw);
    uint32_t base = (sb + 1023u) & ~1023u;

    const int K = F_IN;        // 128
    const int kt = K / 32;     // 4
    const __nv_bfloat16* Ahi = g_Phi;
    const __nv_bfloat16* Alo = g_Plo;
    const __nv_bfloat16* Bhi = g_Uhi + (size_t)layer * USZ;
    const __nv_bfloat16* Blo = g_Ulo + (size_t)layer * USZ;

    int t = threadIdx.x, lane = t & 31, w = t >> 5;
    int wm = (w & 1) * 64, wn = (w >> 1) * 32;
    int m0 = blockIdx.y * 128, n0 = blockIdx.x * 128;

    float c[4][4][4];
#pragma unroll
    for (int i = 0; i < 4; i++)
#pragma unroll
        for (int j = 0; j < 4; j++)
#pragma unroll
            for (int r = 0; r < 4; r++) c[i][j][r] = 0.0f;

    int lrow = (lane & 7) | (((lane >> 3) & 1) << 3);
    int lc = lane >> 4;

    auto issue = [&](int ci, int b) {
        int k0 = ci * 32;
        uint32_t bufb = base + (uint32_t)b * 32768u;
#pragma unroll
        for (int j = 0; j < 2; j++) {
            int id = t + j * 256;
            int row = id >> 2, c16 = id & 3;
            uint32_t off = phys(row, c16);
            int ra = m0 + row;
            int sz = (ra < N_NODES) ? 16 : 0;
            if (ra >= N_NODES) ra = N_NODES - 1;
            cpa16(bufb + off, Ahi + (size_t)ra * K + k0 + c16 * 8, sz);
            cpa16(bufb + 8192u + off, Alo + (size_t)ra * K + k0 + c16 * 8, sz);
            cpa16(bufb + 16384u + off, Bhi + (size_t)(n0 + row) * K + k0 + c16 * 8, 16);
            cpa16(bufb + 24576u + off, Blo + (size_t)(n0 + row) * K + k0 + c16 * 8, 16);
        }
    };

    issue(0, 0);
    asm volatile("cp.async.commit_group;" ::: "memory");

    for (int ci = 0; ci < kt; ci++) {
        if (ci + 1 < kt) {
            issue(ci + 1, (ci + 1) & 1);
            asm volatile("cp.async.commit_group;" ::: "memory");
            asm volatile("cp.async.wait_group 1;" ::: "memory");
        } else {
            asm volatile("cp.async.wait_group 0;" ::: "memory");
        }
        __syncthreads();

        uint32_t buf = base + (uint32_t)(ci & 1) * 32768u;
#pragma unroll
        for (int s = 0; s < 2; s++) {
            uint32_t ah[4][4], al[4][4], bh[4][2], bl[4][2];
#pragma unroll
            for (int mt = 0; mt < 4; mt++) {
                uint32_t off = phys(wm + mt * 16 + lrow, s * 2 + lc);
                ldsm4(ah[mt], buf + off);
                ldsm4(al[mt], buf + 8192u + off);
            }
#pragma unroll
            for (int p = 0; p < 2; p++) {
                uint32_t off = phys(wn + p * 16 + lrow, s * 2 + lc);
                uint32_t r[4];
                ldsm4(r, buf + 16384u + off);
                bh[2 * p][0] = r[0]; bh[2 * p + 1][0] = r[1];
                bh[2 * p][1] = r[2]; bh[2 * p + 1][1] = r[3];
                ldsm4(r, buf + 24576u + off);
                bl[2 * p][0] = r[0]; bl[2 * p + 1][0] = r[1];
                bl[2 * p][1] = r[2]; bl[2 * p + 1][1] = r[3];
            }
#pragma unroll
            for (int mt = 0; mt < 4; mt++)
#pragma unroll
                for (int nt = 0; nt < 4; nt++) {
                    mma16816(c[mt][nt], ah[mt], bh[nt]);
                    mma16816(c[mt][nt], ah[mt], bl[nt]);
                    mma16816(c[mt][nt], al[mt], bh[nt]);
                }
        }
        __syncthreads();
    }

    // epilogue: h = gemm + bias + sum_t q_t(row) * e_t(col), write g_H at coloff
    const float* qp[3] = {nullptr, nullptr, nullptr};
    const float* ep[3] = {nullptr, nullptr, nullptr};
    int nterm = layer;
    if (layer == 1)      { qp[0] = g_q[0]; ep[0] = g_c[0]; }
    else if (layer == 2) { qp[0] = g_q[1]; ep[0] = g_c[3]; qp[1] = g_q[0]; ep[1] = g_c[1]; }
    else if (layer == 3) { qp[0] = g_q[2]; ep[0] = g_c[5]; qp[1] = g_q[1]; ep[1] = g_c[4];
                           qp[2] = g_q[0]; ep[2] = g_c[2]; }
    int coloff = layer * HID;

    int er = lane >> 2, ec = (lane & 3) * 2;
#pragma unroll
    for (int mt = 0; mt < 4; mt++) {
        int r0 = m0 + wm + mt * 16 + er;
        int r1 = r0 + 8;
        float q0[3] = {0.f, 0.f, 0.f}, q1[3] = {0.f, 0.f, 0.f};
        for (int tt = 0; tt < nterm; tt++) {
            if (r0 < N_NODES) q0[tt] = qp[tt][r0];
            if (r1 < N_NODES) q1[tt] = qp[tt][r1];
        }
#pragma unroll
        for (int nt = 0; nt < 4; nt++) {
            int col = n0 + wn + nt * 8 + ec;
            float b0 = bias[col], b1v = bias[col + 1];
            float v00 = c[mt][nt][0] + b0, v01 = c[mt][nt][1] + b1v;
            float v10 = c[mt][nt][2] + b0, v11 = c[mt][nt][3] + b1v;
            for (int tt = 0; tt < nterm; tt++) {
                float e0 = ep[tt][col], e1 = ep[tt][col + 1];
                v00 += q0[tt] * e0; v01 += q0[tt] * e1;
                v10 += q1[tt] * e0; v11 += q1[tt] * e1;
            }
            if (r0 < N_NODES)
                *(float2*)&g_H[(size_t)r0 * HCAT + coloff + col] = make_float2(v00, v01);
            if (r1 < N_NODES)
                *(float2*)&g_H[(size_t)r1 * HCAT + coloff + col] = make_float2(v10, v11);
        }
    }
}

// ---------------- pooling: out = [segmax(H), segmean(H>0)] -----------------
__global__ void k_pool(float* __restrict__ out) {
    int col = blockIdx.x * blockDim.x + threadIdx.x;
    int g   = blockIdx.y;
    int i0 = g_gstart[g], i1 = g_gstart[g + 1];
    float mx = neg_inf();
    float pos = 0.0f;
    for (int i = i0; i < i1; i++) {
        float v = g_H[(size_t)i * HCAT + col];
        mx = fmaxf(mx, v);
        pos += (v > 0.0f) ? 1.0f : 0.0f;
    }
    int cnt = i1 - i0;
    out[(size_t)g * (2 * HCAT) + col] = mx;
    out[(size_t)g * (2 * HCAT) + HCAT + col] = (cnt > 0) ? pos / (float)cnt : 0.0f;
}

// ---------------- launch ----------------------------------------------------
extern "C" void kernel_launch(void* const* d_in, const int* in_sizes, int n_in,
                              void* d_out, int out_size) {
    const float* x     = (const float*)d_in[0];
    const int*   ei    = (const int*)d_in[1];
    const int*   batch = (const int*)d_in[2];
    // d_in[3]=lin_W, d_in[4]=lin_b : dead code in reference
    const float* W1 = (const float*)d_in[5];  const float* b1 = (const float*)d_in[6];
    const float* W2 = (const float*)d_in[7];  const float* b2 = (const float*)d_in[8];
    const float* W3 = (const float*)d_in[9];  const float* b3 = (const float*)d_in[10];
    const float* W4 = (const float*)d_in[11]; const float* b4 = (const float*)d_in[12];
    float* out = (float*)d_out;

    cudaFuncSetAttribute(k_mma_p, cudaFuncAttributeMaxDynamicSharedMemorySize, SMB);

    const int TB = 256;
    // graph preprocessing
    k_init<<<(N_NODES + TB - 1) / TB, TB>>>();
    k_count<<<(N_EDGES + TB - 1) / TB, TB>>>(ei, batch);
    k_scan_rows<<<1, 512>>>();
    k_edges_fill<<<(N_EDGES + TB - 1) / TB, TB>>>(ei);
    k_scan_g<<<1, N_GRAPHS>>>();

    // weight chain: U1=W1, U2=W2W1, U3=W3U2, U4=W4U3 (+ bf16 splits)
    k_convW1<<<(HID * (F_IN / 4) + 255) / 256, 256>>>(W1);
    dim3 wg(F_IN / 32, HID / 32);   // (4,16)
    k_wprod<<<wg, 256>>>(W2, W1, 1, 0, 0, 1);
    k_wprod<<<wg, 256>>>(W3, nullptr, 0, 0, 1, 2);
    k_wprod<<<wg, 256>>>(W4, nullptr, 0, 1, 0, 3);

    // bias chain: c21=W2b1, c32=W3b2, c43=W4b3, c31=W3c21, c42=W4c32, c41=W4c31
    k_matvec<<<HID, 128>>>(W2, b1, 1, 0, 0);
    k_matvec<<<HID, 128>>>(W3, b2, 1, 0, 1);
    k_matvec<<<HID, 128>>>(W4, b3, 1, 0, 2);
    k_matvec<<<HID, 128>>>(W3, nullptr, 0, 0, 3);
    k_matvec<<<HID, 128>>>(W4, nullptr, 0, 1, 4);
    k_matvec<<<HID, 128>>>(W4, nullptr, 0, 3, 5);

    // P/q chain + per-layer GEMM
    dim3 mg(HID / 128, (N_NODES + 127) / 128);       // (4, 157)
    int sg = (N_NODES * 32 + 255) / 256;             // warp per node

    k_spmm_p<<<sg, 256>>>(x, 0);
    k_mma_p<<<mg, 256, SMB>>>(0, b1);
    k_spmm_p<<<sg, 256>>>(x, 1);
    k_mma_p<<<mg, 256, SMB>>>(1, b2);
    k_spmm_p<<<sg, 256>>>(x, 2);
    k_mma_p<<<mg, 256, SMB>>>(2, b3);
    k_spmm_p<<<sg, 256>>>(x, 3);
    k_mma_p<<<mg, 256, SMB>>>(3, b4);

    dim3 pgrid(HCAT / 256, N_GRAPHS);
    k_pool<<<pgrid, 256>>>(out);
}